// round 13
// baseline (speedup 1.0000x reference)
#include <cuda_runtime.h>

// FSUConv2d via SWAR byte-parallel stochastic-bit counting — converged kernel
// (R9 structure, proven 51.7-52.0us total / 49.2us main at the BW roofline).
// - PDL overlap: gate-word prep runs concurrently with main's prologue
//   (threshold table built in-kernel straight from w_bin).
// - Main: persistent (592 = 148x4 exactly-resident), warp-level (b, o-quad)
//   units, 6x LDG.128 bursts, SWAR byte compare (pack+BREV+borrow-SWAR+POPC),
//   packed dual counters -> 2x REDUX, __stcs write-once outputs.
// Traffic = irreducible 307MB idx stream @ ~6.2TB/s achieved -> ~49us floor.

#define NB    2048
#define OCH   64
#define CKK   288
#define NQ    72           // CKK / 4
#define HMASK 0x80808080u
#define GRID  592          // 148 SMs x 4 resident CTAs (even: o-half invariant)
#define WHALF (GRID / 2 * 8)   // 2368 warps per o-half
#define UNITS (NB * 8)         // 16384 units per o-half (b x o-quad)

__device__ unsigned g_gw [NB * NQ];    // ib gate bits at bit7, byte-reversed per quad
__device__ float    g_bias[OCH];       // bias bit as float

// ---- prep: gate words + bias only -------------------------------------------
__global__ void prep(const float* __restrict__ x,
                     const float* __restrict__ b_bin, const float* __restrict__ rng,
                     const int* __restrict__ brdx)
{
    int t = blockIdx.x * blockDim.x + threadIdx.x;
    if (t < NB * NQ) {
        int b = t / NQ, q = t % NQ;
        int n = b >> 8, hw = b & 255, h = hw >> 4, w = hw & 15;
        unsigned gw = 0u;
#pragma unroll
        for (int j = 0; j < 4; ++j) {
            int k  = q * 4 + (3 - j);
            int c  = k / 9;
            int r  = k - c * 9;
            int kh = r / 3;
            int kw = r - kh * 3;
            int hh = h + kh - 1, ww = w + kw - 1;
            float v = 0.0f;
            if ((unsigned)hh < 16u && (unsigned)ww < 16u)
                v = x[((n * 32 + c) << 8) + (hh << 4) + ww];
            if (v > 0.5f) gw |= 0x80u << (8 * j);
        }
        g_gw[t] = gw;
        if (t < OCH)
            g_bias[t] = (b_bin[t] > rng[brdx[t] & 255]) ? 1.0f : 0.0f;
    }
    // allow the dependent (main) grid to start launching
    asm volatile("griddepcontrol.launch_dependents;");
}

// per-byte unsigned a<b at bit7 of each byte (other bit positions garbage)
__device__ __forceinline__ unsigned swar_lt(unsigned a, unsigned b) {
    unsigned s = (a | HMASK) - (b & ~HMASK);   // bit7 per byte: a_low >= b_low
    return (~a & b) | (~(a ^ b) & ~s);         // single LOP3
}

// ---- main: persistent; warp-level units (b, o-quad) within block's o-half ---
__global__ void __launch_bounds__(256, 4)
fsu_main(const int4* __restrict__ i1, const int4* __restrict__ i0,
         const float* __restrict__ w_bin, float* __restrict__ out)
{
    __shared__ uint2 s_twal[32 * NQ];     // thresholds for this block's o-half

    int bid   = blockIdx.x;
    int obase = (bid & 1) * 32;           // invariant under even GRID stride
    int tid   = threadIdx.x;

    // Build threshold table straight from w_bin (independent of prep -> runs
    // concurrently with prep under PDL).
#pragma unroll
    for (int j = 0; j < (32 * NQ) / 256; ++j) {
        int i = tid + j * 256;
        int o = obase + i / NQ, q = i - (i / NQ) * NQ;
        const float4 wv = *(const float4*)(w_bin + o * CKK + q * 4);
        float tvf[4] = {wv.x, wv.y, wv.z, wv.w};
        unsigned tw = 0u, alw = 0u;
#pragma unroll
        for (int jj = 0; jj < 4; ++jj) {
            int tv = (int)tvf[3 - jj];                   // exact int in [0,256]
            unsigned tc = tv > 255 ? 255u : (unsigned)tv;
            tw |= tc << (8 * jj);
            if (tv >= 256) alw |= 0x80u << (8 * jj);
        }
        s_twal[i] = make_uint2(tw, alw);
    }
    __syncthreads();

    // wait for prep's g_gw / g_bias to be visible
    asm volatile("griddepcontrol.wait;");

    int w    = tid >> 5;
    int lane = tid & 31;
    int hwid = (bid >> 1) * 8 + w;        // warp id within this o-half pool

    for (int u = hwid; u < UNITS; u += WHALF) {
        int b  = u >> 3;
        int qw = u & 7;                   // o-quad within half
        int o0 = obase + qw * 4;

        const int4* p1 = i1 + (b * OCH + o0) * NQ + lane;  // 4608B contiguous/warp
        const int4* p0 = i0 + (b * OCH + o0) * NQ + lane;
        const unsigned* gwrow = g_gw + b * NQ;             // L2-resident (589KB)

        unsigned c01 = 0u, c23 = 0u;      // packed counters: lo16 = even cell

#pragma unroll
        for (int s = 0; s < 3; ++s) {
            // burst: 6 LDG.128 back-to-back
            int4 a1[3], a0[3];
#pragma unroll
            for (int j = 0; j < 3; ++j) {
                a1[j] = __ldcs(p1 + (s * 3 + j) * 32);
                a0[j] = __ldcs(p0 + (s * 3 + j) * 32);
            }

#pragma unroll
            for (int j = 0; j < 3; ++j) {
                const int it = s * 3 + j;
                const int g  = it * 32;

                unsigned pk1 = __byte_perm(__byte_perm(a1[j].x, a1[j].y, 0x0040),
                                           __byte_perm(a1[j].z, a1[j].w, 0x0040), 0x5410);
                unsigned pk0 = __byte_perm(__byte_perm(a0[j].x, a0[j].y, 0x0040),
                                           __byte_perm(a0[j].z, a0[j].w, 0x0040), 0x5410);
                unsigned r1 = __brev(pk1);     // rev8 of all 4 bytes at once
                unsigned r0 = __brev(pk0);

                // o-cell (0..3) for this lane's quad (compile-time split points)
                const int cA  = g / 72;
                const int thr = (cA + 1) * 72 - g;
                const int qb  = g - cA * 72;

                int q;
                if (thr >= 32) q = qb + lane;
                else           q = (lane < thr) ? (qb + lane) : (qb + lane - 72);
                unsigned gt = __ldg(gwrow + q);

                uint2 twal = s_twal[qw * 288 + g + lane];

                unsigned lt1 = swar_lt(r1, twal.x);
                unsigned lt0 = swar_lt(r0, twal.x);
                unsigned f1  = (lt1 | twal.y) & gt;     // ib * bit1         (bit7-clean)
                unsigned nf0 = (lt0 | twal.y) | gt;     // ~((1-ib)*(1-bit0))
                unsigned p   = (unsigned)__popc(f1 | (~nf0 & HMASK));

                // accumulate into packed counters (cell 0/2 -> lo16, 1/3 -> hi16)
                if (thr >= 32) {
                    if (cA == 0)      c01 += p;
                    else if (cA == 1) c01 += p << 16;
                    else if (cA == 2) c23 += p;
                    else              c23 += p << 16;
                } else {
                    unsigned plo = (lane < thr) ? p : 0u;
                    unsigned phi = p - plo;
                    if (cA == 0)      c01 += plo + (phi << 16);
                    else if (cA == 1) { c01 += plo << 16; c23 += phi; }
                    else              c23 += plo + (phi << 16);
                }
            }
        }

        c01 = __reduce_add_sync(0xffffffffu, c01);
        c23 = __reduce_add_sync(0xffffffffu, c23);

        if (lane == 0) {
            int n = b >> 8, hw = b & 255;
            float* ob = out + (n * OCH + o0) * 256 + hw;
            __stcs(ob,       (float)(c01 & 0xffffu) + g_bias[o0]);
            __stcs(ob + 256, (float)(c01 >> 16)     + g_bias[o0 + 1]);
            __stcs(ob + 512, (float)(c23 & 0xffffu) + g_bias[o0 + 2]);
            __stcs(ob + 768, (float)(c23 >> 16)     + g_bias[o0 + 3]);
        }
    }
}

// ---- launch -----------------------------------------------------------------
extern "C" void kernel_launch(void* const* d_in, const int* in_sizes, int n_in,
                              void* d_out, int out_size) {
    const float* x     = (const float*)d_in[0];   // [8,32,16,16]
    const float* w_bin = (const float*)d_in[1];   // [64,288]
    const float* b_bin = (const float*)d_in[2];   // [64]
    const float* rng   = (const float*)d_in[3];   // [256]
    const int4*  i1    = (const int4*) d_in[4];   // [2048,64,288]
    const int4*  i0    = (const int4*) d_in[5];   // [2048,64,288]
    const int*   brdx  = (const int*)  d_in[6];   // [64]
    float* out = (float*)d_out;                   // [8,64,16,16]

    prep<<<(NB * NQ + 255) / 256, 256>>>(x, b_bin, rng, brdx);

    // main, programmatically overlapped with prep (PDL)
    cudaLaunchConfig_t cfg = {};
    cfg.gridDim  = dim3(GRID, 1, 1);
    cfg.blockDim = dim3(256, 1, 1);
    cudaLaunchAttribute at[1];
    at[0].id = cudaLaunchAttributeProgrammaticStreamSerialization;
    at[0].val.programmaticStreamSerializationAllowed = 1;
    cfg.attrs = at;
    cfg.numAttrs = 1;
    cudaLaunchKernelEx(&cfg, fsu_main, i1, i0, w_bin, out);
}

// round 16
// speedup vs baseline: 1.0131x; 1.0131x over previous
#include <cuda_runtime.h>

// FSUConv2d via SWAR byte-parallel stochastic-bit counting — FINAL kernel
// (R9/R13 structure; passed 3x at 51.7-52.0us total / ~49us main, which is
// the HBM roofline: traffic == irreducible 307MB idx stream @ ~6.26TB/s).
// R15's bench failure used this exact source and R13 passed with it -> the
// failure was broker-pod infra, not the kernel. Resubmitting unchanged.
//
// Structure:
// - PDL overlap: gate-word/bias prep runs concurrently with main's prologue
//   (threshold table built in-kernel straight from w_bin).
// - Main: persistent (592 = 148x4 exactly-resident), warp-level (b, o-quad)
//   units, 6x LDG.128 evict-first bursts, SWAR byte compare
//   (PRMT pack + BREV + borrow-SWAR + POPC), packed dual counters -> 2x REDUX,
//   __stcs write-once outputs, gate table served from L2.

#define NB    2048
#define OCH   64
#define CKK   288
#define NQ    72           // CKK / 4
#define HMASK 0x80808080u
#define GRID  592          // 148 SMs x 4 resident CTAs (even: o-half invariant)
#define WHALF (GRID / 2 * 8)   // 2368 warps per o-half
#define UNITS (NB * 8)         // 16384 units per o-half (b x o-quad)

__device__ unsigned g_gw [NB * NQ];    // ib gate bits at bit7, byte-reversed per quad
__device__ float    g_bias[OCH];       // bias bit as float

// ---- prep: gate words + bias only -------------------------------------------
__global__ void prep(const float* __restrict__ x,
                     const float* __restrict__ b_bin, const float* __restrict__ rng,
                     const int* __restrict__ brdx)
{
    int t = blockIdx.x * blockDim.x + threadIdx.x;
    if (t < NB * NQ) {
        int b = t / NQ, q = t % NQ;
        int n = b >> 8, hw = b & 255, h = hw >> 4, w = hw & 15;
        unsigned gw = 0u;
#pragma unroll
        for (int j = 0; j < 4; ++j) {
            int k  = q * 4 + (3 - j);
            int c  = k / 9;
            int r  = k - c * 9;
            int kh = r / 3;
            int kw = r - kh * 3;
            int hh = h + kh - 1, ww = w + kw - 1;
            float v = 0.0f;
            if ((unsigned)hh < 16u && (unsigned)ww < 16u)
                v = x[((n * 32 + c) << 8) + (hh << 4) + ww];
            if (v > 0.5f) gw |= 0x80u << (8 * j);
        }
        g_gw[t] = gw;
        if (t < OCH)
            g_bias[t] = (b_bin[t] > rng[brdx[t] & 255]) ? 1.0f : 0.0f;
    }
    // allow the dependent (main) grid to start launching
    asm volatile("griddepcontrol.launch_dependents;");
}

// per-byte unsigned a<b at bit7 of each byte (other bit positions garbage)
__device__ __forceinline__ unsigned swar_lt(unsigned a, unsigned b) {
    unsigned s = (a | HMASK) - (b & ~HMASK);   // bit7 per byte: a_low >= b_low
    return (~a & b) | (~(a ^ b) & ~s);         // single LOP3
}

// ---- main: persistent; warp-level units (b, o-quad) within block's o-half ---
__global__ void __launch_bounds__(256, 4)
fsu_main(const int4* __restrict__ i1, const int4* __restrict__ i0,
         const float* __restrict__ w_bin, float* __restrict__ out)
{
    __shared__ uint2 s_twal[32 * NQ];     // thresholds for this block's o-half

    int bid   = blockIdx.x;
    int obase = (bid & 1) * 32;           // invariant under even GRID stride
    int tid   = threadIdx.x;

    // Build threshold table straight from w_bin (independent of prep -> runs
    // concurrently with prep under PDL).
#pragma unroll
    for (int j = 0; j < (32 * NQ) / 256; ++j) {
        int i = tid + j * 256;
        int o = obase + i / NQ, q = i - (i / NQ) * NQ;
        const float4 wv = *(const float4*)(w_bin + o * CKK + q * 4);
        float tvf[4] = {wv.x, wv.y, wv.z, wv.w};
        unsigned tw = 0u, alw = 0u;
#pragma unroll
        for (int jj = 0; jj < 4; ++jj) {
            int tv = (int)tvf[3 - jj];                   // exact int in [0,256]
            unsigned tc = tv > 255 ? 255u : (unsigned)tv;
            tw |= tc << (8 * jj);
            if (tv >= 256) alw |= 0x80u << (8 * jj);
        }
        s_twal[i] = make_uint2(tw, alw);
    }
    __syncthreads();

    // wait for prep's g_gw / g_bias to be visible
    asm volatile("griddepcontrol.wait;");

    int w    = tid >> 5;
    int lane = tid & 31;
    int hwid = (bid >> 1) * 8 + w;        // warp id within this o-half pool

    for (int u = hwid; u < UNITS; u += WHALF) {
        int b  = u >> 3;
        int qw = u & 7;                   // o-quad within half
        int o0 = obase + qw * 4;

        const int4* p1 = i1 + (b * OCH + o0) * NQ + lane;  // 4608B contiguous/warp
        const int4* p0 = i0 + (b * OCH + o0) * NQ + lane;
        const unsigned* gwrow = g_gw + b * NQ;             // L2-resident (589KB)

        unsigned c01 = 0u, c23 = 0u;      // packed counters: lo16 = even cell

#pragma unroll
        for (int s = 0; s < 3; ++s) {
            // burst: 6 LDG.128 back-to-back
            int4 a1[3], a0[3];
#pragma unroll
            for (int j = 0; j < 3; ++j) {
                a1[j] = __ldcs(p1 + (s * 3 + j) * 32);
                a0[j] = __ldcs(p0 + (s * 3 + j) * 32);
            }

#pragma unroll
            for (int j = 0; j < 3; ++j) {
                const int it = s * 3 + j;
                const int g  = it * 32;

                unsigned pk1 = __byte_perm(__byte_perm(a1[j].x, a1[j].y, 0x0040),
                                           __byte_perm(a1[j].z, a1[j].w, 0x0040), 0x5410);
                unsigned pk0 = __byte_perm(__byte_perm(a0[j].x, a0[j].y, 0x0040),
                                           __byte_perm(a0[j].z, a0[j].w, 0x0040), 0x5410);
                unsigned r1 = __brev(pk1);     // rev8 of all 4 bytes at once
                unsigned r0 = __brev(pk0);

                // o-cell (0..3) for this lane's quad (compile-time split points)
                const int cA  = g / 72;
                const int thr = (cA + 1) * 72 - g;
                const int qb  = g - cA * 72;

                int q;
                if (thr >= 32) q = qb + lane;
                else           q = (lane < thr) ? (qb + lane) : (qb + lane - 72);
                unsigned gt = __ldg(gwrow + q);

                uint2 twal = s_twal[qw * 288 + g + lane];

                unsigned lt1 = swar_lt(r1, twal.x);
                unsigned lt0 = swar_lt(r0, twal.x);
                unsigned f1  = (lt1 | twal.y) & gt;     // ib * bit1         (bit7-clean)
                unsigned nf0 = (lt0 | twal.y) | gt;     // ~((1-ib)*(1-bit0))
                unsigned p   = (unsigned)__popc(f1 | (~nf0 & HMASK));

                // accumulate into packed counters (cell 0/2 -> lo16, 1/3 -> hi16)
                if (thr >= 32) {
                    if (cA == 0)      c01 += p;
                    else if (cA == 1) c01 += p << 16;
                    else if (cA == 2) c23 += p;
                    else              c23 += p << 16;
                } else {
                    unsigned plo = (lane < thr) ? p : 0u;
                    unsigned phi = p - plo;
                    if (cA == 0)      c01 += plo + (phi << 16);
                    else if (cA == 1) { c01 += plo << 16; c23 += phi; }
                    else              c23 += plo + (phi << 16);
                }
            }
        }

        c01 = __reduce_add_sync(0xffffffffu, c01);
        c23 = __reduce_add_sync(0xffffffffu, c23);

        if (lane == 0) {
            int n = b >> 8, hw = b & 255;
            float* ob = out + (n * OCH + o0) * 256 + hw;
            __stcs(ob,       (float)(c01 & 0xffffu) + g_bias[o0]);
            __stcs(ob + 256, (float)(c01 >> 16)     + g_bias[o0 + 1]);
            __stcs(ob + 512, (float)(c23 & 0xffffu) + g_bias[o0 + 2]);
            __stcs(ob + 768, (float)(c23 >> 16)     + g_bias[o0 + 3]);
        }
    }
}

// ---- launch -----------------------------------------------------------------
extern "C" void kernel_launch(void* const* d_in, const int* in_sizes, int n_in,
                              void* d_out, int out_size) {
    const float* x     = (const float*)d_in[0];   // [8,32,16,16]
    const float* w_bin = (const float*)d_in[1];   // [64,288]
    const float* b_bin = (const float*)d_in[2];   // [64]
    const float* rng   = (const float*)d_in[3];   // [256]
    const int4*  i1    = (const int4*) d_in[4];   // [2048,64,288]
    const int4*  i0    = (const int4*) d_in[5];   // [2048,64,288]
    const int*   brdx  = (const int*)  d_in[6];   // [64]
    float* out = (float*)d_out;                   // [8,64,16,16]

    prep<<<(NB * NQ + 255) / 256, 256>>>(x, b_bin, rng, brdx);

    // main, programmatically overlapped with prep (PDL)
    cudaLaunchConfig_t cfg = {};
    cfg.gridDim  = dim3(GRID, 1, 1);
    cfg.blockDim = dim3(256, 1, 1);
    cudaLaunchAttribute at[1];
    at[0].id = cudaLaunchAttributeProgrammaticStreamSerialization;
    at[0].val.programmaticStreamSerializationAllowed = 1;
    cfg.attrs = at;
    cfg.numAttrs = 1;
    cudaLaunchKernelEx(&cfg, fsu_main, i1, i0, w_bin, out);
}